// round 13
// baseline (speedup 1.0000x reference)
#include <cuda_runtime.h>
#include <cuda_bf16.h>
#include <math.h>
#include <stdint.h>

// Problem dims (fixed)
#define SEQ   512
#define BATCH 64
#define IND   512
#define HID   1024
#define OUTD  512
#define CDIM  1536

#define NCTA  128          // recurrence CTAs: CTA n owns cols c=q*8+jl, j=n*8+jl

typedef unsigned long long u64;

// ---- k_recur smem layout (bytes) ----
#define RW_STRIDE 1032     // W smem row stride (bf16 elems)
#define RH        136      // h smem row stride (bf16 elems)
#define R_WHI 0                       // 32 x 1032 x2B        = 66048
#define R_WLO 66048                   //                      -> 132096
#define R_HB  132096                  // 2 bufs x (hi+lo) x 64x136x2B
#define HBUF_SZ 34816                 // one buf: hi(17408) + lo(17408)
#define R_GACT 201728                 // float[2][64*34]
#define SMEM_R 219136

// ---- k_tgemm smem (3-stage cp.async pipeline) ----
#define TS 40
#define TG_TILE_B (128 * TS * 2)      // 10240 B per tile
#define TG_STAGE_B (4 * TG_TILE_B)    // 40960 B per stage
#define TG_SMEM (3 * TG_STAGE_B)      // 122880 B

// ---------------- scratch ----------------
__device__ float g_Gx  [(size_t)SEQ * NCTA * BATCH * 32];   // [t][n][b][c], c=q*8+jl
__device__ int   g_done;
__device__ __nv_bfloat16 g_Xhi [(size_t)SEQ * BATCH * IND];
__device__ __nv_bfloat16 g_Xlo [(size_t)SEQ * BATCH * IND];
__device__ __nv_bfloat16 g_WAhi[(size_t)4096 * 512];
__device__ __nv_bfloat16 g_WAlo[(size_t)4096 * 512];
__device__ __nv_bfloat16 g_Hhi [(size_t)SEQ * BATCH * HID]; // h for step t at rows t*64+b
__device__ __nv_bfloat16 g_Hlo [(size_t)SEQ * BATCH * HID];
__device__ __nv_bfloat16 g_Wyhi[(size_t)OUTD * HID];
__device__ __nv_bfloat16 g_Wylo[(size_t)OUTD * HID];
__device__ float g_ball[4096];

static __device__ __forceinline__ float sigm(float x) { return 1.0f / (1.0f + __expf(-x)); }

// ---------------- mma.sync / cp.async helpers ----------------
static __device__ __forceinline__ uint32_t smem_u32(const void* p) {
    uint32_t a;
    asm("{ .reg .u64 t; cvta.to.shared.u64 t, %1; cvt.u32.u64 %0, t; }" : "=r"(a) : "l"(p));
    return a;
}
static __device__ __forceinline__ void ldmx4(uint32_t* r, uint32_t addr) {
    asm volatile("ldmatrix.sync.aligned.m8n8.x4.shared.b16 {%0,%1,%2,%3}, [%4];"
                 : "=r"(r[0]), "=r"(r[1]), "=r"(r[2]), "=r"(r[3]) : "r"(addr));
}
static __device__ __forceinline__ void mma_bf16(float* c, const uint32_t* a, const uint32_t* b) {
    asm volatile(
        "mma.sync.aligned.m16n8k16.row.col.f32.bf16.bf16.f32 "
        "{%0,%1,%2,%3}, {%4,%5,%6,%7}, {%8,%9}, {%0,%1,%2,%3};"
        : "+f"(c[0]), "+f"(c[1]), "+f"(c[2]), "+f"(c[3])
        : "r"(a[0]), "r"(a[1]), "r"(a[2]), "r"(a[3]), "r"(b[0]), "r"(b[1]));
}
static __device__ __forceinline__ void cpa16(uint32_t dst, const void* src) {
    asm volatile("cp.async.cg.shared.global [%0], [%1], 16;" :: "r"(dst), "l"(src));
}
#define CPA_COMMIT() asm volatile("cp.async.commit_group;" ::: "memory")
#define CPA_WAIT0()  asm volatile("cp.async.wait_group 0;" ::: "memory")
#define CPA_WAIT1()  asm volatile("cp.async.wait_group 1;" ::: "memory")

__global__ void k_init() { if (threadIdx.x == 0) g_done = 0; }

// =====================================================================
// converters: fp32 -> (bf16 hi, bf16 lo). which: 0=X, 1=Wy
// =====================================================================
__global__ void k_cvt(const float4* __restrict__ src, long n4, int which)
{
    u64 *hi, *lo;
    if (which == 0) { hi = (u64*)g_Xhi;  lo = (u64*)g_Xlo;  }
    else            { hi = (u64*)g_Wyhi; lo = (u64*)g_Wylo; }
    long i = (long)blockIdx.x * blockDim.x + threadIdx.x;
    long stride = (long)gridDim.x * blockDim.x;
    for (; i < n4; i += stride) {
        float4 v = src[i];
        float vv[4] = {v.x, v.y, v.z, v.w};
        __nv_bfloat16 h[4], l[4];
#pragma unroll
        for (int j = 0; j < 4; j++) {
            h[j] = __float2bfloat16(vv[j]);
            l[j] = __float2bfloat16(vv[j] - __bfloat162float(h[j]));
        }
        u64 hp, lp;
        __builtin_memcpy(&hp, h, 8); __builtin_memcpy(&lp, l, 8);
        hi[i] = hp; lo[i] = lp;
    }
}

// gather W_all input part (cols 0..511) + bias into g_WA*, g_ball
__global__ void k_cvt_wall(
    const float* __restrict__ Wf, const float* __restrict__ bf,
    const float* __restrict__ Wi, const float* __restrict__ bi,
    const float* __restrict__ Wo, const float* __restrict__ bo,
    const float* __restrict__ Wg, const float* __restrict__ bg)
{
    int n = blockIdx.x;                 // 0..4095
    int q = n >> 10, j = n & 1023;
    const float* Wq = (q == 0) ? Wf : (q == 1) ? Wi : (q == 2) ? Wo : Wg;
    const float* bq = (q == 0) ? bf : (q == 1) ? bi : (q == 2) ? bo : bg;
    int k = threadIdx.x * 4;
    float4 v = *(const float4*)(Wq + (size_t)j * CDIM + k);
    float vv[4] = {v.x, v.y, v.z, v.w};
    __nv_bfloat16 h[4], l[4];
#pragma unroll
    for (int t = 0; t < 4; t++) {
        h[t] = __float2bfloat16(vv[t]);
        l[t] = __float2bfloat16(vv[t] - __bfloat162float(h[t]));
    }
    u64 hp, lp;
    __builtin_memcpy(&hp, h, 8); __builtin_memcpy(&lp, l, 8);
    *(u64*)(g_WAhi + (size_t)n * 512 + k) = hp;
    *(u64*)(g_WAlo + (size_t)n * 512 + k) = lp;
    if (threadIdx.x == 0) g_ball[n] = bq[j];
}

// =====================================================================
// k_tgemm: split-bf16 mma.sync GEMM, 3-stage cp.async pipeline.
// CTA tile 128x128, 8 warps (4m x 2n), warp tile 32x64, K-chunk 32.
// mode 1: A=X, B=WA, bias=g_ball -> g_Gx permuted; mode 0: A=H,B=Wy -> outp
// =====================================================================
__global__ __launch_bounds__(256) void k_tgemm(
    const float* __restrict__ bias_ext, float* __restrict__ outp, int K, int mode)
{
    extern __shared__ char tgs[];

    const int tid  = threadIdx.x;
    const int lane = tid & 31, w = tid >> 5;
    const int wm = w & 3, wn = w >> 2;
    const int m0 = blockIdx.y * 128, n0 = blockIdx.x * 128;

    const __nv_bfloat16* bases[4];
    const float* bias;
    if (mode == 1) {
        bases[0] = g_Xhi  + (size_t)m0 * K;  bases[1] = g_Xlo  + (size_t)m0 * K;
        bases[2] = g_WAhi + (size_t)n0 * K;  bases[3] = g_WAlo + (size_t)n0 * K;
        bias = g_ball;
    } else {
        bases[0] = g_Hhi  + (size_t)m0 * K;  bases[1] = g_Hlo  + (size_t)m0 * K;
        bases[2] = g_Wyhi + (size_t)n0 * K;  bases[3] = g_Wylo + (size_t)n0 * K;
        bias = bias_ext;
    }

    float acc[2][8][4];
#pragma unroll
    for (int mt = 0; mt < 2; mt++)
#pragma unroll
        for (int nt = 0; nt < 8; nt++)
#pragma unroll
            for (int f = 0; f < 4; f++) acc[mt][nt][f] = 0.0f;

    const int arow = ((lane >> 3) & 1) * 8 + (lane & 7);
    const int akof = ((lane >> 4) & 1) * 8;
    const int brow = ((lane >> 4) & 1) * 8 + (lane & 7);
    const int bkof = ((lane >> 3) & 1) * 8;

    // loader: 8 cp.async(16B) per thread per chunk
    int ld_tile[8], ld_r[8], ld_slot[8];
#pragma unroll
    for (int i = 0; i < 8; i++) {
        int e = tid + i * 256;
        ld_tile[i] = e >> 9; ld_r[i] = (e >> 2) & 127; ld_slot[i] = e & 3;
    }

    const int chunks = K >> 5;

#define TG_ISSUE(stage, ch)                                                     \
    do {                                                                        \
        char* sb = tgs + (stage) * TG_STAGE_B;                                  \
        _Pragma("unroll")                                                       \
        for (int i = 0; i < 8; i++) {                                           \
            uint32_t dst = smem_u32(sb + ld_tile[i] * TG_TILE_B                 \
                                    + (ld_r[i] * TS + ld_slot[i] * 8) * 2);     \
            cpa16(dst, bases[ld_tile[i]] + (size_t)ld_r[i] * K                  \
                       + (ch) * 32 + ld_slot[i] * 8);                           \
        }                                                                       \
        CPA_COMMIT();                                                           \
    } while (0)

    TG_ISSUE(0, 0);
    if (chunks > 1) TG_ISSUE(1, 1); else CPA_COMMIT();

    for (int ch = 0; ch < chunks; ch++) {
        if (ch + 1 < chunks) CPA_WAIT1(); else CPA_WAIT0();
        __syncthreads();
        if (ch + 2 < chunks) TG_ISSUE((ch + 2) % 3, ch + 2);

        char* sb = tgs + (ch % 3) * TG_STAGE_B;
        __nv_bfloat16* smA[2] = { (__nv_bfloat16*)(sb),
                                  (__nv_bfloat16*)(sb + TG_TILE_B) };
        __nv_bfloat16* smB[2] = { (__nv_bfloat16*)(sb + 2 * TG_TILE_B),
                                  (__nv_bfloat16*)(sb + 3 * TG_TILE_B) };

#pragma unroll
        for (int kstep = 0; kstep < 2; kstep++) {
            uint32_t afr[2][2][4];
#pragma unroll
            for (int mt = 0; mt < 2; mt++)
#pragma unroll
                for (int s = 0; s < 2; s++)
                    ldmx4(afr[mt][s], smem_u32(
                        smA[s] + (wm * 32 + mt * 16 + arow) * TS + akof + kstep * 16));
            uint32_t bfr[8][2][2];
#pragma unroll
            for (int ntp = 0; ntp < 4; ntp++)
#pragma unroll
                for (int s = 0; s < 2; s++) {
                    uint32_t r4[4];
                    ldmx4(r4, smem_u32(
                        smB[s] + (wn * 64 + ntp * 16 + brow) * TS + bkof + kstep * 16));
                    bfr[ntp * 2][s][0]     = r4[0];
                    bfr[ntp * 2][s][1]     = r4[1];
                    bfr[ntp * 2 + 1][s][0] = r4[2];
                    bfr[ntp * 2 + 1][s][1] = r4[3];
                }
#pragma unroll
            for (int mt = 0; mt < 2; mt++)
#pragma unroll
                for (int nt = 0; nt < 8; nt++) {
                    mma_bf16(acc[mt][nt], afr[mt][0], bfr[nt][0]);
                    mma_bf16(acc[mt][nt], afr[mt][1], bfr[nt][0]);
                    mma_bf16(acc[mt][nt], afr[mt][0], bfr[nt][1]);
                }
        }
        __syncthreads();
    }

    const int mrow = lane >> 2;
    const int ncol = (lane & 3) * 2;
#pragma unroll
    for (int mt = 0; mt < 2; mt++) {
#pragma unroll
        for (int nt = 0; nt < 8; nt++) {
            int nloc = wn * 64 + nt * 8 + ncol;
            int nglb = n0 + nloc;
            float2 bv = {bias[nglb], bias[nglb + 1]};
#pragma unroll
            for (int half = 0; half < 2; half++) {
                int gm = m0 + wm * 32 + mt * 16 + mrow + half * 8;
                float2 v;
                v.x = acc[mt][nt][half * 2 + 0] + bv.x;
                v.y = acc[mt][nt][half * 2 + 1] + bv.y;
                if (mode == 0) {
                    *(float2*)(outp + (size_t)gm * OUTD + nglb) = v;
                } else {
                    int q  = n0 >> 10;
                    int jj = (n0 & 1023) + nloc;
                    int ntidx = jj >> 3, jl = jj & 7;
                    int tt = gm >> 6, b = gm & 63;
                    *(float2*)(g_Gx + (((size_t)tt * NCTA + ntidx) * 64 + b) * 32
                               + q * 8 + jl) = v;
                }
            }
        }
    }
}

// =====================================================================
// k_recur: PERSISTENT recurrence, split-bf16 mma.sync.
// 128 CTAs x 512 thr (16 warps: 4m x 2n x 2kg). cp.async double-buffered
// h chunks; W resident bf16 hi/lo in smem; c in regs; 1 global sync/step.
// =====================================================================
__global__ __launch_bounds__(512, 1) void k_recur(
    const float* __restrict__ Wf, const float* __restrict__ Wi,
    const float* __restrict__ Wo, const float* __restrict__ Wg)
{
    extern __shared__ char smem[];
    __nv_bfloat16* whi = (__nv_bfloat16*)(smem + R_WHI);   // [32 c][1024 k] stride 1032
    __nv_bfloat16* wlo = (__nv_bfloat16*)(smem + R_WLO);
    float*         gact = (float*)(smem + R_GACT);          // [2 kg][64 b][34]

    const int tid = threadIdx.x;
    const int n   = blockIdx.x;

    // ---- one-time: convert W slice to bf16 hi/lo in smem ----
#pragma unroll 4
    for (int i = 0; i < 16; i++) {
        int e = tid + i * 512;              // 0..8191, float4 each
        int row = e >> 8;                   // 0..31  (c = q*8+jl)
        int kp  = (e & 255) * 4;
        int q = row >> 3, jl = row & 7;
        const float* Wq = (q == 0) ? Wf : (q == 1) ? Wi : (q == 2) ? Wo : Wg;
        float4 v = *(const float4*)(Wq + (size_t)(n * 8 + jl) * CDIM + IND + kp);
        float vv[4] = {v.x, v.y, v.z, v.w};
        __nv_bfloat16 h4[4], l4[4];
#pragma unroll
        for (int u = 0; u < 4; u++) {
            h4[u] = __float2bfloat16(vv[u]);
            l4[u] = __float2bfloat16(vv[u] - __bfloat162float(h4[u]));
        }
        u64 hp, lp;
        __builtin_memcpy(&hp, h4, 8); __builtin_memcpy(&lp, l4, 8);
        *(u64*)(whi + (size_t)row * RW_STRIDE + kp) = hp;
        *(u64*)(wlo + (size_t)row * RW_STRIDE + kp) = lp;
    }
    __syncthreads();

    const int lane = tid & 31, wid = tid >> 5;
    const int kg = wid & 1;
    const int wn = (wid >> 1) & 1;
    const int wm = wid >> 2;
    const int arow = ((lane >> 3) & 1) * 8 + (lane & 7);
    const int akof = ((lane >> 4) & 1) * 8;
    const int brow = ((lane >> 4) & 1) * 8 + (lane & 7);
    const int bkof = ((lane >> 3) & 1) * 8;
    const int mrow = lane >> 2;
    const int ncol = (lane & 3) * 2;

    // h-chunk loader geometry: 2 rows per thread (hi+lo each, 16B)
    int lr[2], lsl[2];
#pragma unroll
    for (int i = 0; i < 2; i++) {
        int e = tid + i * 512;              // 0..1023
        lr[i] = e >> 4; lsl[i] = (e & 15) * 8;
    }

    const int b_act = tid >> 3, jl_act = tid & 7;
    float cst = 0.0f;

    for (int t = 0; t < SEQ; t++) {
        const float* gxb = g_Gx + (((size_t)t * NCTA + n) * 64 + b_act) * 32 + jl_act;
        float gx0 = gxb[0], gx1 = gxb[8], gx2 = gxb[16], gx3 = gxb[24];

        if (t > 0) {
            if (tid == 0) {
                int target = NCTA * t, v;
                do {
                    asm volatile("ld.acquire.gpu.global.s32 %0, [%1];"
                                 : "=r"(v) : "l"(&g_done) : "memory");
                } while (v < target);
            }
            __syncthreads();

            const __nv_bfloat16* Ghi = g_Hhi + (size_t)(t - 1) * 65536;
            const __nv_bfloat16* Glo = g_Hlo + (size_t)(t - 1) * 65536;

#define RC_ISSUE(buf, ch)                                                        \
    do {                                                                         \
        char* hb = smem + R_HB + (buf) * HBUF_SZ;                                \
        _Pragma("unroll")                                                        \
        for (int i = 0; i < 2; i++) {                                            \
            uint32_t d0 = smem_u32(hb + ((size_t)lr[i] * RH + lsl[i]) * 2);      \
            cpa16(d0, Ghi + (size_t)lr[i] * 1024 + (ch) * 128 + lsl[i]);         \
            uint32_t d1 = smem_u32(hb + 17408 + ((size_t)lr[i] * RH + lsl[i]) * 2);\
            cpa16(d1, Glo + (size_t)lr[i] * 1024 + (ch) * 128 + lsl[i]);         \
        }                                                                        \
        CPA_COMMIT();                                                            \
    } while (0)

            float acc0[4] = {0.f, 0.f, 0.f, 0.f};
            float acc1[4] = {0.f, 0.f, 0.f, 0.f};

            RC_ISSUE(0, 0);

#pragma unroll 1
            for (int ch = 0; ch < 8; ch++) {
                CPA_WAIT0();
                __syncthreads();
                if (ch < 7) RC_ISSUE((ch + 1) & 1, ch + 1);

                __nv_bfloat16* Hh = (__nv_bfloat16*)(smem + R_HB + (ch & 1) * HBUF_SZ);
                __nv_bfloat16* Hl = Hh + 8704;   // +17408 B
#pragma unroll
                for (int kk = 0; kk < 4; kk++) {
                    int kid = kg * 4 + kk;
                    uint32_t ah[4], al[4], bh[4], bl[4];
                    ldmx4(ah, smem_u32(Hh + (size_t)(wm * 16 + arow) * RH + kid * 16 + akof));
                    ldmx4(al, smem_u32(Hl + (size_t)(wm * 16 + arow) * RH + kid * 16 + akof));
                    int wk = ch * 128 + kid * 16 + bkof;
                    ldmx4(bh, smem_u32(whi + (size_t)(wn * 16 + brow) * RW_STRIDE + wk));
                    ldmx4(bl, smem_u32(wlo + (size_t)(wn * 16 + brow) * RW_STRIDE + wk));
                    mma_bf16(acc0, ah, bh);
                    mma_bf16(acc1, ah, bh + 2);
                    mma_bf16(acc0, al, bh);
                    mma_bf16(acc1, al, bh + 2);
                    mma_bf16(acc0, ah, bl);
                    mma_bf16(acc1, ah, bl + 2);
                }
            }

            // gate pre-activations -> gact[kg][b][c]
            {
                float* ga = gact + kg * 2176;
                int r0 = wm * 16 + mrow;
                int c0 = wn * 16 + ncol;
                *(float2*)(ga + (size_t)r0 * 34 + c0)            = *(float2*)&acc0[0];
                *(float2*)(ga + (size_t)(r0 + 8) * 34 + c0)      = *(float2*)&acc0[2];
                *(float2*)(ga + (size_t)r0 * 34 + c0 + 8)        = *(float2*)&acc1[0];
                *(float2*)(ga + (size_t)(r0 + 8) * 34 + c0 + 8)  = *(float2*)&acc1[2];
            }
            __syncthreads();
        }

        // ---- fused activations + cell update + h write ----
        {
            float fv = gx0, iv = gx1, ov = gx2, gv = gx3;
            if (t > 0) {
                const float* ga0 = gact + (size_t)b_act * 34 + jl_act;
                const float* ga1 = ga0 + 2176;
                fv += ga0[0]  + ga1[0];
                iv += ga0[8]  + ga1[8];
                ov += ga0[16] + ga1[16];
                gv += ga0[24] + ga1[24];
            }
            float f = sigm(fv), ii = sigm(iv), oo = sigm(ov), gt = tanhf(gv);
            cst = f * cst + ii * gt;
            float hv = oo * tanhf(cst);
            __nv_bfloat16 hh = __float2bfloat16(hv);
            size_t idx = ((size_t)t * 64 + b_act) * 1024 + n * 8 + jl_act;
            g_Hhi[idx] = hh;
            g_Hlo[idx] = __float2bfloat16(hv - __bfloat162float(hh));
        }

        __syncthreads();
        if (tid == 0)
            asm volatile("red.release.gpu.global.add.s32 [%0], %1;"
                         :: "l"(&g_done), "r"(1) : "memory");
    }
}

// ---------------- launch ----------------
extern "C" void kernel_launch(void* const* d_in, const int* in_sizes, int n_in,
                              void* d_out, int out_size) {
    const float* x  = (const float*)d_in[0];
    const float* Wf = (const float*)d_in[1];
    const float* bf = (const float*)d_in[2];
    const float* Wi = (const float*)d_in[3];
    const float* bi = (const float*)d_in[4];
    const float* Wo = (const float*)d_in[5];
    const float* bo = (const float*)d_in[6];
    const float* Wg = (const float*)d_in[7];
    const float* bg = (const float*)d_in[8];
    const float* Wy = (const float*)d_in[9];
    const float* by = (const float*)d_in[10];
    float* out = (float*)d_out;

    cudaFuncSetAttribute(k_recur, cudaFuncAttributeMaxDynamicSharedMemorySize, SMEM_R);
    cudaFuncSetAttribute(k_tgemm, cudaFuncAttributeMaxDynamicSharedMemorySize, TG_SMEM);

    k_init<<<1, 32>>>();

    // converts for the bulk GEMMs
    k_cvt<<<4096, 256>>>((const float4*)x, (long)SEQ * BATCH * IND / 4, 0);
    k_cvt_wall<<<4096, 128>>>(Wf, bf, Wi, bi, Wo, bo, Wg, bg);
    k_cvt<<<512, 256>>>((const float4*)Wy, (long)OUTD * HID / 4, 1);

    // pregemm: Gx = X @ W_all^T + b_all -> permuted [t][n][b][c]
    k_tgemm<<<dim3(32, 256), 256, TG_SMEM>>>(nullptr, nullptr, IND, 1);

    // recurrence (tensor-core, persistent)
    k_recur<<<NCTA, 512, SMEM_R>>>(Wf, Wi, Wo, Wg);

    // out = H @ Wy^T + by  (A = g_Hhi/g_Hlo written by k_recur)
    k_tgemm<<<dim3(4, 256), 256, TG_SMEM>>>(by, out, HID, 0);
}

// round 15
// speedup vs baseline: 1.1724x; 1.1724x over previous
#include <cuda_runtime.h>
#include <cuda_fp16.h>
#include <math.h>
#include <stdint.h>

// Problem dims (fixed)
#define SEQ   512
#define BATCH 64
#define IND   512
#define HID   1024
#define OUTD  512
#define CDIM  1536

#define NCTA  128          // recurrence CTAs: CTA n owns cols c=q*8+jl, j=n*8+jl

typedef unsigned long long u64;

// ---- k_recur smem layout (bytes) ----
#define RW_STRIDE 1032     // W smem row stride (fp16 elems)
#define RH        136      // h smem row stride (fp16 elems)
#define R_W   0                       // 32 x 1032 x 2B = 66048
#define R_HB  66048                   // 2 bufs x (hi+lo) x 64x136x2B
#define HBUF_SZ 34816                 // one buf: hi(17408) + lo(17408)
#define R_GACT 135680                 // float[2][64*34] = 17408
#define SMEM_R 153088

// ---- k_tgemm smem (3-stage cp.async pipeline, 3 tiles/stage) ----
#define TS 40
#define TG_TILE_B (128 * TS * 2)      // 10240 B per tile
#define TG_STAGE_B (3 * TG_TILE_B)    // 30720 B per stage (A_hi, A_lo, B)
#define TG_SMEM (3 * TG_STAGE_B)      // 92160 B

// ---------------- scratch ----------------
__device__ float g_Gx  [(size_t)SEQ * NCTA * BATCH * 32];   // [t][n][b][c], c=q*8+jl
__device__ int   g_done;
__device__ __half g_Xhi [(size_t)SEQ * BATCH * IND];
__device__ __half g_Xlo [(size_t)SEQ * BATCH * IND];
__device__ __half g_WAh [(size_t)4096 * 512];               // W_all input part, single fp16
__device__ __half g_Hhi [(size_t)SEQ * BATCH * HID];        // h for step t at rows t*64+b
__device__ __half g_Hlo [(size_t)SEQ * BATCH * HID];
__device__ __half g_Wyh [(size_t)OUTD * HID];               // Wy single fp16
__device__ float g_ball[4096];

static __device__ __forceinline__ float sigm(float x) { return 1.0f / (1.0f + __expf(-x)); }

// ---------------- mma.sync / cp.async helpers ----------------
static __device__ __forceinline__ uint32_t smem_u32(const void* p) {
    uint32_t a;
    asm("{ .reg .u64 t; cvta.to.shared.u64 t, %1; cvt.u32.u64 %0, t; }" : "=r"(a) : "l"(p));
    return a;
}
static __device__ __forceinline__ void ldmx4(uint32_t* r, uint32_t addr) {
    asm volatile("ldmatrix.sync.aligned.m8n8.x4.shared.b16 {%0,%1,%2,%3}, [%4];"
                 : "=r"(r[0]), "=r"(r[1]), "=r"(r[2]), "=r"(r[3]) : "r"(addr));
}
static __device__ __forceinline__ void mma_f16(float* c, const uint32_t* a, const uint32_t* b) {
    asm volatile(
        "mma.sync.aligned.m16n8k16.row.col.f32.f16.f16.f32 "
        "{%0,%1,%2,%3}, {%4,%5,%6,%7}, {%8,%9}, {%0,%1,%2,%3};"
        : "+f"(c[0]), "+f"(c[1]), "+f"(c[2]), "+f"(c[3])
        : "r"(a[0]), "r"(a[1]), "r"(a[2]), "r"(a[3]), "r"(b[0]), "r"(b[1]));
}
static __device__ __forceinline__ void cpa16(uint32_t dst, const void* src) {
    asm volatile("cp.async.cg.shared.global [%0], [%1], 16;" :: "r"(dst), "l"(src));
}
#define CPA_COMMIT() asm volatile("cp.async.commit_group;" ::: "memory")
#define CPA_WAIT0()  asm volatile("cp.async.wait_group 0;" ::: "memory")
#define CPA_WAIT1()  asm volatile("cp.async.wait_group 1;" ::: "memory")

__global__ void k_init() { if (threadIdx.x == 0) g_done = 0; }

// =====================================================================
// converters
// =====================================================================
// X: fp32 -> (fp16 hi, fp16 lo)
__global__ void k_cvt_split(const float4* __restrict__ src, long n4)
{
    u64* hi = (u64*)g_Xhi; u64* lo = (u64*)g_Xlo;
    long i = (long)blockIdx.x * blockDim.x + threadIdx.x;
    long stride = (long)gridDim.x * blockDim.x;
    for (; i < n4; i += stride) {
        float4 v = src[i];
        float vv[4] = {v.x, v.y, v.z, v.w};
        __half h[4], l[4];
#pragma unroll
        for (int j = 0; j < 4; j++) {
            h[j] = __float2half(vv[j]);
            l[j] = __float2half(vv[j] - __half2float(h[j]));
        }
        u64 hp, lp;
        __builtin_memcpy(&hp, h, 8); __builtin_memcpy(&lp, l, 8);
        hi[i] = hp; lo[i] = lp;
    }
}

// Wy: fp32 -> single fp16
__global__ void k_cvt_one(const float4* __restrict__ src, long n4)
{
    u64* dst = (u64*)g_Wyh;
    long i = (long)blockIdx.x * blockDim.x + threadIdx.x;
    long stride = (long)gridDim.x * blockDim.x;
    for (; i < n4; i += stride) {
        float4 v = src[i];
        float vv[4] = {v.x, v.y, v.z, v.w};
        __half h[4];
#pragma unroll
        for (int j = 0; j < 4; j++) h[j] = __float2half(vv[j]);
        u64 hp; __builtin_memcpy(&hp, h, 8);
        dst[i] = hp;
    }
}

// gather W_all input part (cols 0..511, single fp16) + bias
__global__ void k_cvt_wall(
    const float* __restrict__ Wf, const float* __restrict__ bf,
    const float* __restrict__ Wi, const float* __restrict__ bi,
    const float* __restrict__ Wo, const float* __restrict__ bo,
    const float* __restrict__ Wg, const float* __restrict__ bg)
{
    int n = blockIdx.x;                 // 0..4095
    int q = n >> 10, j = n & 1023;
    const float* Wq = (q == 0) ? Wf : (q == 1) ? Wi : (q == 2) ? Wo : Wg;
    const float* bq = (q == 0) ? bf : (q == 1) ? bi : (q == 2) ? bo : bg;
    int k = threadIdx.x * 4;
    float4 v = *(const float4*)(Wq + (size_t)j * CDIM + k);
    float vv[4] = {v.x, v.y, v.z, v.w};
    __half h[4];
#pragma unroll
    for (int t = 0; t < 4; t++) h[t] = __float2half(vv[t]);
    u64 hp; __builtin_memcpy(&hp, h, 8);
    *(u64*)(g_WAh + (size_t)n * 512 + k) = hp;
    if (threadIdx.x == 0) g_ball[n] = bq[j];
}

// =====================================================================
// k_tgemm: C = (Ahi+Alo) @ B^T + bias, fp16 2-pass mma.sync,
// 3-stage cp.async pipeline. CTA tile 128x128, 8 warps (4m x 2n).
// mode 1: A=X, B=WAh -> g_Gx permuted;  mode 0: A=H, B=Wyh -> outp rows
// =====================================================================
__global__ __launch_bounds__(256) void k_tgemm(
    const float* __restrict__ bias_ext, float* __restrict__ outp, int K, int mode)
{
    extern __shared__ char tgs[];

    const int tid  = threadIdx.x;
    const int lane = tid & 31, w = tid >> 5;
    const int wm = w & 3, wn = w >> 2;
    const int m0 = blockIdx.y * 128, n0 = blockIdx.x * 128;

    const __half* bases[3];
    const float* bias;
    if (mode == 1) {
        bases[0] = g_Xhi + (size_t)m0 * K;  bases[1] = g_Xlo + (size_t)m0 * K;
        bases[2] = g_WAh + (size_t)n0 * K;
        bias = g_ball;
    } else {
        bases[0] = g_Hhi + (size_t)m0 * K;  bases[1] = g_Hlo + (size_t)m0 * K;
        bases[2] = g_Wyh + (size_t)n0 * K;
        bias = bias_ext;
    }

    float acc[2][8][4];
#pragma unroll
    for (int mt = 0; mt < 2; mt++)
#pragma unroll
        for (int nt = 0; nt < 8; nt++)
#pragma unroll
            for (int f = 0; f < 4; f++) acc[mt][nt][f] = 0.0f;

    const int arow = ((lane >> 3) & 1) * 8 + (lane & 7);
    const int akof = ((lane >> 4) & 1) * 8;
    const int brow = ((lane >> 4) & 1) * 8 + (lane & 7);
    const int bkof = ((lane >> 3) & 1) * 8;

    // loader: 6 cp.async(16B) per thread per chunk (3 tiles x 128 r x 4 slots)
    int ld_tile[6], ld_r[6], ld_slot[6];
#pragma unroll
    for (int i = 0; i < 6; i++) {
        int e = tid + i * 256;
        ld_tile[i] = e >> 9; ld_r[i] = (e >> 2) & 127; ld_slot[i] = e & 3;
    }

    const int chunks = K >> 5;

#define TG_ISSUE(stage, ch)                                                     \
    do {                                                                        \
        char* sb = tgs + (stage) * TG_STAGE_B;                                  \
        _Pragma("unroll")                                                       \
        for (int i = 0; i < 6; i++) {                                           \
            uint32_t dst = smem_u32(sb + ld_tile[i] * TG_TILE_B                 \
                                    + (ld_r[i] * TS + ld_slot[i] * 8) * 2);     \
            cpa16(dst, bases[ld_tile[i]] + (size_t)ld_r[i] * K                  \
                       + (ch) * 32 + ld_slot[i] * 8);                           \
        }                                                                       \
        CPA_COMMIT();                                                           \
    } while (0)

    TG_ISSUE(0, 0);
    if (chunks > 1) TG_ISSUE(1, 1); else CPA_COMMIT();

    for (int ch = 0; ch < chunks; ch++) {
        if (ch + 1 < chunks) CPA_WAIT1(); else CPA_WAIT0();
        __syncthreads();
        if (ch + 2 < chunks) TG_ISSUE((ch + 2) % 3, ch + 2);

        char* sb = tgs + (ch % 3) * TG_STAGE_B;
        __half* smA[2] = { (__half*)(sb), (__half*)(sb + TG_TILE_B) };
        __half* smB   = (__half*)(sb + 2 * TG_TILE_B);

#pragma unroll
        for (int kstep = 0; kstep < 2; kstep++) {
            uint32_t afr[2][2][4];   // [mt][hi/lo][4]
#pragma unroll
            for (int mt = 0; mt < 2; mt++)
#pragma unroll
                for (int s = 0; s < 2; s++)
                    ldmx4(afr[mt][s], smem_u32(
                        smA[s] + (wm * 32 + mt * 16 + arow) * TS + akof + kstep * 16));
            uint32_t bfr[8][2];      // [nt][2]
#pragma unroll
            for (int ntp = 0; ntp < 4; ntp++) {
                uint32_t r4[4];
                ldmx4(r4, smem_u32(
                    smB + (wn * 64 + ntp * 16 + brow) * TS + bkof + kstep * 16));
                bfr[ntp * 2][0]     = r4[0];
                bfr[ntp * 2][1]     = r4[1];
                bfr[ntp * 2 + 1][0] = r4[2];
                bfr[ntp * 2 + 1][1] = r4[3];
            }
#pragma unroll
            for (int mt = 0; mt < 2; mt++)
#pragma unroll
                for (int nt = 0; nt < 8; nt++) {
                    mma_f16(acc[mt][nt], afr[mt][0], bfr[nt]);  // hi pass
                    mma_f16(acc[mt][nt], afr[mt][1], bfr[nt]);  // lo pass
                }
        }
        __syncthreads();
    }

    const int mrow = lane >> 2;
    const int ncol = (lane & 3) * 2;
#pragma unroll
    for (int mt = 0; mt < 2; mt++) {
#pragma unroll
        for (int nt = 0; nt < 8; nt++) {
            int nloc = wn * 64 + nt * 8 + ncol;
            int nglb = n0 + nloc;
            float2 bv = {bias[nglb], bias[nglb + 1]};
#pragma unroll
            for (int half = 0; half < 2; half++) {
                int gm = m0 + wm * 32 + mt * 16 + mrow + half * 8;
                float2 v;
                v.x = acc[mt][nt][half * 2 + 0] + bv.x;
                v.y = acc[mt][nt][half * 2 + 1] + bv.y;
                if (mode == 0) {
                    *(float2*)(outp + (size_t)gm * OUTD + nglb) = v;
                } else {
                    int q  = n0 >> 10;
                    int jj = (n0 & 1023) + nloc;
                    int ntidx = jj >> 3, jl = jj & 7;
                    int tt = gm >> 6, b = gm & 63;
                    *(float2*)(g_Gx + (((size_t)tt * NCTA + ntidx) * 64 + b) * 32
                               + q * 8 + jl) = v;
                }
            }
        }
    }
}

// =====================================================================
// k_recur: PERSISTENT recurrence, fp16 2-pass mma.sync.
// 128 CTAs x 512 thr (16 warps: 4m x 2n x 2kg). cp.async double-buffered
// h chunks (fp16 hi/lo); W single fp16 resident in smem; c in regs;
// one acquire/release global sync per step.
// =====================================================================
__global__ __launch_bounds__(512, 1) void k_recur(
    const float* __restrict__ Wf, const float* __restrict__ Wi,
    const float* __restrict__ Wo, const float* __restrict__ Wg)
{
    extern __shared__ char smem[];
    __half* wsm  = (__half*)(smem + R_W);      // [32 c][1024 k] stride 1032
    float*  gact = (float*)(smem + R_GACT);    // [2 kg][64 b][34]

    const int tid = threadIdx.x;
    const int n   = blockIdx.x;

    // ---- one-time: convert W slice to single fp16 in smem ----
#pragma unroll 4
    for (int i = 0; i < 16; i++) {
        int e = tid + i * 512;              // 0..8191, float4 each
        int row = e >> 8;                   // 0..31  (c = q*8+jl)
        int kp  = (e & 255) * 4;
        int q = row >> 3, jl = row & 7;
        const float* Wq = (q == 0) ? Wf : (q == 1) ? Wi : (q == 2) ? Wo : Wg;
        float4 v = *(const float4*)(Wq + (size_t)(n * 8 + jl) * CDIM + IND + kp);
        float vv[4] = {v.x, v.y, v.z, v.w};
        __half h4[4];
#pragma unroll
        for (int u = 0; u < 4; u++) h4[u] = __float2half(vv[u]);
        u64 hp; __builtin_memcpy(&hp, h4, 8);
        *(u64*)(wsm + (size_t)row * RW_STRIDE + kp) = hp;
    }
    __syncthreads();

    const int lane = tid & 31, wid = tid >> 5;
    const int kg = wid & 1;
    const int wn = (wid >> 1) & 1;
    const int wm = wid >> 2;
    const int arow = ((lane >> 3) & 1) * 8 + (lane & 7);
    const int akof = ((lane >> 4) & 1) * 8;
    const int brow = ((lane >> 4) & 1) * 8 + (lane & 7);
    const int bkof = ((lane >> 3) & 1) * 8;
    const int mrow = lane >> 2;
    const int ncol = (lane & 3) * 2;

    // h-chunk loader geometry: 2 rows per thread (hi+lo each, 16B)
    int lr[2], lsl[2];
#pragma unroll
    for (int i = 0; i < 2; i++) {
        int e = tid + i * 512;              // 0..1023
        lr[i] = e >> 4; lsl[i] = (e & 15) * 8;
    }

    const int b_act = tid >> 3, jl_act = tid & 7;
    float cst = 0.0f;

    for (int t = 0; t < SEQ; t++) {
        const float* gxb = g_Gx + (((size_t)t * NCTA + n) * 64 + b_act) * 32 + jl_act;
        float gx0 = gxb[0], gx1 = gxb[8], gx2 = gxb[16], gx3 = gxb[24];

        if (t > 0) {
            if (tid == 0) {
                int target = NCTA * t, v;
                do {
                    asm volatile("ld.acquire.gpu.global.s32 %0, [%1];"
                                 : "=r"(v) : "l"(&g_done) : "memory");
                } while (v < target);
            }
            __syncthreads();

            const __half* Ghi = g_Hhi + (size_t)(t - 1) * 65536;
            const __half* Glo = g_Hlo + (size_t)(t - 1) * 65536;

#define RC_ISSUE(buf, ch)                                                        \
    do {                                                                         \
        char* hb = smem + R_HB + (buf) * HBUF_SZ;                                \
        _Pragma("unroll")                                                        \
        for (int i = 0; i < 2; i++) {                                            \
            uint32_t d0 = smem_u32(hb + ((size_t)lr[i] * RH + lsl[i]) * 2);      \
            cpa16(d0, Ghi + (size_t)lr[i] * 1024 + (ch) * 128 + lsl[i]);         \
            uint32_t d1 = smem_u32(hb + 17408 + ((size_t)lr[i] * RH + lsl[i]) * 2);\
            cpa16(d1, Glo + (size_t)lr[i] * 1024 + (ch) * 128 + lsl[i]);         \
        }                                                                        \
        CPA_COMMIT();                                                            \
    } while (0)

            float acc0[4] = {0.f, 0.f, 0.f, 0.f};
            float acc1[4] = {0.f, 0.f, 0.f, 0.f};

            RC_ISSUE(0, 0);

#pragma unroll 1
            for (int ch = 0; ch < 8; ch++) {
                CPA_WAIT0();
                __syncthreads();
                if (ch < 7) RC_ISSUE((ch + 1) & 1, ch + 1);

                __half* Hh = (__half*)(smem + R_HB + (ch & 1) * HBUF_SZ);
                __half* Hl = Hh + 8704;   // +17408 B
#pragma unroll
                for (int kk = 0; kk < 4; kk++) {
                    int kid = kg * 4 + kk;
                    uint32_t ah[4], al[4], bh[4];
                    ldmx4(ah, smem_u32(Hh + (size_t)(wm * 16 + arow) * RH + kid * 16 + akof));
                    ldmx4(al, smem_u32(Hl + (size_t)(wm * 16 + arow) * RH + kid * 16 + akof));
                    int wk = ch * 128 + kid * 16 + bkof;
                    ldmx4(bh, smem_u32(wsm + (size_t)(wn * 16 + brow) * RW_STRIDE + wk));
                    mma_f16(acc0, ah, bh);
                    mma_f16(acc1, ah, bh + 2);
                    mma_f16(acc0, al, bh);
                    mma_f16(acc1, al, bh + 2);
                }
            }

            // gate pre-activations -> gact[kg][b][c]
            {
                float* ga = gact + kg * 2176;
                int r0 = wm * 16 + mrow;
                int c0 = wn * 16 + ncol;
                *(float2*)(ga + (size_t)r0 * 34 + c0)            = *(float2*)&acc0[0];
                *(float2*)(ga + (size_t)(r0 + 8) * 34 + c0)      = *(float2*)&acc0[2];
                *(float2*)(ga + (size_t)r0 * 34 + c0 + 8)        = *(float2*)&acc1[0];
                *(float2*)(ga + (size_t)(r0 + 8) * 34 + c0 + 8)  = *(float2*)&acc1[2];
            }
            __syncthreads();
        }

        // ---- fused activations + cell update + h write ----
        {
            float fv = gx0, iv = gx1, ov = gx2, gv = gx3;
            if (t > 0) {
                const float* ga0 = gact + (size_t)b_act * 34 + jl_act;
                const float* ga1 = ga0 + 2176;
                fv += ga0[0]  + ga1[0];
                iv += ga0[8]  + ga1[8];
                ov += ga0[16] + ga1[16];
                gv += ga0[24] + ga1[24];
            }
            float f = sigm(fv), ii = sigm(iv), oo = sigm(ov), gt = tanhf(gv);
            cst = f * cst + ii * gt;
            float hv = oo * tanhf(cst);
            __half hh = __float2half(hv);
            size_t idx = ((size_t)t * 64 + b_act) * 1024 + n * 8 + jl_act;
            g_Hhi[idx] = hh;
            g_Hlo[idx] = __float2half(hv - __half2float(hh));
        }

        __syncthreads();
        if (tid == 0)
            asm volatile("red.release.gpu.global.add.s32 [%0], %1;"
                         :: "l"(&g_done), "r"(1) : "memory");
    }
}

// ---------------- launch ----------------
extern "C" void kernel_launch(void* const* d_in, const int* in_sizes, int n_in,
                              void* d_out, int out_size) {
    const float* x  = (const float*)d_in[0];
    const float* Wf = (const float*)d_in[1];
    const float* bf = (const float*)d_in[2];
    const float* Wi = (const float*)d_in[3];
    const float* bi = (const float*)d_in[4];
    const float* Wo = (const float*)d_in[5];
    const float* bo = (const float*)d_in[6];
    const float* Wg = (const float*)d_in[7];
    const float* bg = (const float*)d_in[8];
    const float* Wy = (const float*)d_in[9];
    const float* by = (const float*)d_in[10];
    float* out = (float*)d_out;

    cudaFuncSetAttribute(k_recur, cudaFuncAttributeMaxDynamicSharedMemorySize, SMEM_R);
    cudaFuncSetAttribute(k_tgemm, cudaFuncAttributeMaxDynamicSharedMemorySize, TG_SMEM);

    k_init<<<1, 32>>>();

    // converts for the bulk GEMMs
    k_cvt_split<<<4096, 256>>>((const float4*)x, (long)SEQ * BATCH * IND / 4);
    k_cvt_wall<<<4096, 128>>>(Wf, bf, Wi, bi, Wo, bo, Wg, bg);
    k_cvt_one<<<512, 256>>>((const float4*)Wy, (long)OUTD * HID / 4);

    // pregemm: Gx = X @ W_all^T + b_all -> permuted [t][n][b][c]
    k_tgemm<<<dim3(32, 256), 256, TG_SMEM>>>(nullptr, nullptr, IND, 1);

    // recurrence (tensor-core, persistent)
    k_recur<<<NCTA, 512, SMEM_R>>>(Wf, Wi, Wo, Wg);

    // out = H @ Wy^T + by  (A = g_Hhi/g_Hlo written by k_recur)
    k_tgemm<<<dim3(4, 256), 256, TG_SMEM>>>(by, out, HID, 0);
}

// round 16
// speedup vs baseline: 1.4080x; 1.2009x over previous
#include <cuda_runtime.h>
#include <cuda_fp16.h>
#include <math.h>
#include <stdint.h>

// Problem dims (fixed)
#define SEQ   512
#define BATCH 64
#define IND   512
#define HID   1024
#define OUTD  512
#define CDIM  1536

#define NCTA  128          // recurrence CTAs: CTA n owns cols c=q*8+jl, j=n*8+jl

typedef unsigned long long u64;

// ---- k_recur smem layout (bytes) ----
#define RW_STRIDE 1032     // W smem row stride (fp16 elems)
#define RH        136      // h smem row stride (fp16 elems)
#define R_W   0                       // 32 x 1032 x 2B = 66048
#define R_HB  66048                   // 2 bufs x (hi only) x 64x136x2B
#define HBUF_SZ 17408                 // one buf: hi only
#define R_GACT 100864                 // float[2][64*34] = 17408
#define SMEM_R 118272

// ---- k_tgemm smem (3-stage cp.async pipeline, 3 tiles/stage) ----
#define TS 40
#define TG_TILE_B (128 * TS * 2)      // 10240 B per tile
#define TG_STAGE_B (3 * TG_TILE_B)    // 30720 B per stage (A_hi, A_lo, B)
#define TG_SMEM (3 * TG_STAGE_B)      // 92160 B

// ---------------- scratch ----------------
__device__ float g_Gx  [(size_t)SEQ * NCTA * BATCH * 32];   // [t][n][b][c], c=q*8+jl
__device__ int   g_done;
__device__ __half g_Xhi [(size_t)SEQ * BATCH * IND];
__device__ __half g_Xlo [(size_t)SEQ * BATCH * IND];
__device__ __half g_WAh [(size_t)4096 * 512];               // W_all input part, single fp16
__device__ __half g_Hhi [(size_t)SEQ * BATCH * HID];        // h for step t at rows t*64+b
__device__ __half g_Hlo [(size_t)SEQ * BATCH * HID];        // residual (out-GEMM only)
__device__ __half g_Wyh [(size_t)OUTD * HID];               // Wy single fp16
__device__ float g_ball[4096];

static __device__ __forceinline__ float sigm(float x) { return 1.0f / (1.0f + __expf(-x)); }

// ---------------- mma.sync / cp.async helpers ----------------
static __device__ __forceinline__ uint32_t smem_u32(const void* p) {
    uint32_t a;
    asm("{ .reg .u64 t; cvta.to.shared.u64 t, %1; cvt.u32.u64 %0, t; }" : "=r"(a) : "l"(p));
    return a;
}
static __device__ __forceinline__ void ldmx4(uint32_t* r, uint32_t addr) {
    asm volatile("ldmatrix.sync.aligned.m8n8.x4.shared.b16 {%0,%1,%2,%3}, [%4];"
                 : "=r"(r[0]), "=r"(r[1]), "=r"(r[2]), "=r"(r[3]) : "r"(addr));
}
static __device__ __forceinline__ void mma_f16(float* c, const uint32_t* a, const uint32_t* b) {
    asm volatile(
        "mma.sync.aligned.m16n8k16.row.col.f32.f16.f16.f32 "
        "{%0,%1,%2,%3}, {%4,%5,%6,%7}, {%8,%9}, {%0,%1,%2,%3};"
        : "+f"(c[0]), "+f"(c[1]), "+f"(c[2]), "+f"(c[3])
        : "r"(a[0]), "r"(a[1]), "r"(a[2]), "r"(a[3]), "r"(b[0]), "r"(b[1]));
}
static __device__ __forceinline__ void cpa16(uint32_t dst, const void* src) {
    asm volatile("cp.async.cg.shared.global [%0], [%1], 16;" :: "r"(dst), "l"(src));
}
#define CPA_COMMIT() asm volatile("cp.async.commit_group;" ::: "memory")
#define CPA_WAIT0()  asm volatile("cp.async.wait_group 0;" ::: "memory")
#define CPA_WAIT1()  asm volatile("cp.async.wait_group 1;" ::: "memory")

__global__ void k_init() { if (threadIdx.x == 0) g_done = 0; }

// =====================================================================
// converters
// =====================================================================
// X: fp32 -> (fp16 hi, fp16 lo)
__global__ void k_cvt_split(const float4* __restrict__ src, long n4)
{
    u64* hi = (u64*)g_Xhi; u64* lo = (u64*)g_Xlo;
    long i = (long)blockIdx.x * blockDim.x + threadIdx.x;
    long stride = (long)gridDim.x * blockDim.x;
    for (; i < n4; i += stride) {
        float4 v = src[i];
        float vv[4] = {v.x, v.y, v.z, v.w};
        __half h[4], l[4];
#pragma unroll
        for (int j = 0; j < 4; j++) {
            h[j] = __float2half(vv[j]);
            l[j] = __float2half(vv[j] - __half2float(h[j]));
        }
        u64 hp, lp;
        __builtin_memcpy(&hp, h, 8); __builtin_memcpy(&lp, l, 8);
        hi[i] = hp; lo[i] = lp;
    }
}

// Wy: fp32 -> single fp16
__global__ void k_cvt_one(const float4* __restrict__ src, long n4)
{
    u64* dst = (u64*)g_Wyh;
    long i = (long)blockIdx.x * blockDim.x + threadIdx.x;
    long stride = (long)gridDim.x * blockDim.x;
    for (; i < n4; i += stride) {
        float4 v = src[i];
        float vv[4] = {v.x, v.y, v.z, v.w};
        __half h[4];
#pragma unroll
        for (int j = 0; j < 4; j++) h[j] = __float2half(vv[j]);
        u64 hp; __builtin_memcpy(&hp, h, 8);
        dst[i] = hp;
    }
}

// gather W_all input part (cols 0..511, single fp16) + bias
__global__ void k_cvt_wall(
    const float* __restrict__ Wf, const float* __restrict__ bf,
    const float* __restrict__ Wi, const float* __restrict__ bi,
    const float* __restrict__ Wo, const float* __restrict__ bo,
    const float* __restrict__ Wg, const float* __restrict__ bg)
{
    int n = blockIdx.x;                 // 0..4095
    int q = n >> 10, j = n & 1023;
    const float* Wq = (q == 0) ? Wf : (q == 1) ? Wi : (q == 2) ? Wo : Wg;
    const float* bq = (q == 0) ? bf : (q == 1) ? bi : (q == 2) ? bo : bg;
    int k = threadIdx.x * 4;
    float4 v = *(const float4*)(Wq + (size_t)j * CDIM + k);
    float vv[4] = {v.x, v.y, v.z, v.w};
    __half h[4];
#pragma unroll
    for (int t = 0; t < 4; t++) h[t] = __float2half(vv[t]);
    u64 hp; __builtin_memcpy(&hp, h, 8);
    *(u64*)(g_WAh + (size_t)n * 512 + k) = hp;
    if (threadIdx.x == 0) g_ball[n] = bq[j];
}

// =====================================================================
// k_tgemm: C = (Ahi+Alo) @ B^T + bias, fp16 2-pass mma.sync,
// 3-stage cp.async pipeline. CTA tile 128x128, 8 warps (4m x 2n).
// mode 1: A=X, B=WAh -> g_Gx permuted;  mode 0: A=H, B=Wyh -> outp rows
// =====================================================================
__global__ __launch_bounds__(256) void k_tgemm(
    const float* __restrict__ bias_ext, float* __restrict__ outp, int K, int mode)
{
    extern __shared__ char tgs[];

    const int tid  = threadIdx.x;
    const int lane = tid & 31, w = tid >> 5;
    const int wm = w & 3, wn = w >> 2;
    const int m0 = blockIdx.y * 128, n0 = blockIdx.x * 128;

    const __half* bases[3];
    const float* bias;
    if (mode == 1) {
        bases[0] = g_Xhi + (size_t)m0 * K;  bases[1] = g_Xlo + (size_t)m0 * K;
        bases[2] = g_WAh + (size_t)n0 * K;
        bias = g_ball;
    } else {
        bases[0] = g_Hhi + (size_t)m0 * K;  bases[1] = g_Hlo + (size_t)m0 * K;
        bases[2] = g_Wyh + (size_t)n0 * K;
        bias = bias_ext;
    }

    float acc[2][8][4];
#pragma unroll
    for (int mt = 0; mt < 2; mt++)
#pragma unroll
        for (int nt = 0; nt < 8; nt++)
#pragma unroll
            for (int f = 0; f < 4; f++) acc[mt][nt][f] = 0.0f;

    const int arow = ((lane >> 3) & 1) * 8 + (lane & 7);
    const int akof = ((lane >> 4) & 1) * 8;
    const int brow = ((lane >> 4) & 1) * 8 + (lane & 7);
    const int bkof = ((lane >> 3) & 1) * 8;

    // loader: 6 cp.async(16B) per thread per chunk (3 tiles x 128 r x 4 slots)
    int ld_tile[6], ld_r[6], ld_slot[6];
#pragma unroll
    for (int i = 0; i < 6; i++) {
        int e = tid + i * 256;
        ld_tile[i] = e >> 9; ld_r[i] = (e >> 2) & 127; ld_slot[i] = e & 3;
    }

    const int chunks = K >> 5;

#define TG_ISSUE(stage, ch)                                                     \
    do {                                                                        \
        char* sb = tgs + (stage) * TG_STAGE_B;                                  \
        _Pragma("unroll")                                                       \
        for (int i = 0; i < 6; i++) {                                           \
            uint32_t dst = smem_u32(sb + ld_tile[i] * TG_TILE_B                 \
                                    + (ld_r[i] * TS + ld_slot[i] * 8) * 2);     \
            cpa16(dst, bases[ld_tile[i]] + (size_t)ld_r[i] * K                  \
                       + (ch) * 32 + ld_slot[i] * 8);                           \
        }                                                                       \
        CPA_COMMIT();                                                           \
    } while (0)

    TG_ISSUE(0, 0);
    if (chunks > 1) TG_ISSUE(1, 1); else CPA_COMMIT();

    for (int ch = 0; ch < chunks; ch++) {
        if (ch + 1 < chunks) CPA_WAIT1(); else CPA_WAIT0();
        __syncthreads();
        if (ch + 2 < chunks) TG_ISSUE((ch + 2) % 3, ch + 2);

        char* sb = tgs + (ch % 3) * TG_STAGE_B;
        __half* smA[2] = { (__half*)(sb), (__half*)(sb + TG_TILE_B) };
        __half* smB   = (__half*)(sb + 2 * TG_TILE_B);

#pragma unroll
        for (int kstep = 0; kstep < 2; kstep++) {
            uint32_t afr[2][2][4];   // [mt][hi/lo][4]
#pragma unroll
            for (int mt = 0; mt < 2; mt++)
#pragma unroll
                for (int s = 0; s < 2; s++)
                    ldmx4(afr[mt][s], smem_u32(
                        smA[s] + (wm * 32 + mt * 16 + arow) * TS + akof + kstep * 16));
            uint32_t bfr[8][2];      // [nt][2]
#pragma unroll
            for (int ntp = 0; ntp < 4; ntp++) {
                uint32_t r4[4];
                ldmx4(r4, smem_u32(
                    smB + (wn * 64 + ntp * 16 + brow) * TS + bkof + kstep * 16));
                bfr[ntp * 2][0]     = r4[0];
                bfr[ntp * 2][1]     = r4[1];
                bfr[ntp * 2 + 1][0] = r4[2];
                bfr[ntp * 2 + 1][1] = r4[3];
            }
#pragma unroll
            for (int mt = 0; mt < 2; mt++)
#pragma unroll
                for (int nt = 0; nt < 8; nt++) {
                    mma_f16(acc[mt][nt], afr[mt][0], bfr[nt]);  // hi pass
                    mma_f16(acc[mt][nt], afr[mt][1], bfr[nt]);  // lo pass
                }
        }
        __syncthreads();
    }

    const int mrow = lane >> 2;
    const int ncol = (lane & 3) * 2;
#pragma unroll
    for (int mt = 0; mt < 2; mt++) {
#pragma unroll
        for (int nt = 0; nt < 8; nt++) {
            int nloc = wn * 64 + nt * 8 + ncol;
            int nglb = n0 + nloc;
            float2 bv = {bias[nglb], bias[nglb + 1]};
#pragma unroll
            for (int half = 0; half < 2; half++) {
                int gm = m0 + wm * 32 + mt * 16 + mrow + half * 8;
                float2 v;
                v.x = acc[mt][nt][half * 2 + 0] + bv.x;
                v.y = acc[mt][nt][half * 2 + 1] + bv.y;
                if (mode == 0) {
                    *(float2*)(outp + (size_t)gm * OUTD + nglb) = v;
                } else {
                    int q  = n0 >> 10;
                    int jj = (n0 & 1023) + nloc;
                    int ntidx = jj >> 3, jl = jj & 7;
                    int tt = gm >> 6, b = gm & 63;
                    *(float2*)(g_Gx + (((size_t)tt * NCTA + ntidx) * 64 + b) * 32
                               + q * 8 + jl) = v;
                }
            }
        }
    }
}

// =====================================================================
// k_recur: PERSISTENT recurrence, fp16 SINGLE-pass mma.sync.
// 128 CTAs x 512 thr (16 warps: 4m x 2n x 2kg). cp.async double-buffered
// h chunks (fp16 hi only); W single fp16 resident in smem; c in regs;
// one acquire/release global sync per step.
// =====================================================================
__global__ __launch_bounds__(512, 1) void k_recur(
    const float* __restrict__ Wf, const float* __restrict__ Wi,
    const float* __restrict__ Wo, const float* __restrict__ Wg)
{
    extern __shared__ char smem[];
    __half* wsm  = (__half*)(smem + R_W);      // [32 c][1024 k] stride 1032
    float*  gact = (float*)(smem + R_GACT);    // [2 kg][64 b][34]

    const int tid = threadIdx.x;
    const int n   = blockIdx.x;

    // ---- one-time: convert W slice to single fp16 in smem ----
#pragma unroll 4
    for (int i = 0; i < 16; i++) {
        int e = tid + i * 512;              // 0..8191, float4 each
        int row = e >> 8;                   // 0..31  (c = q*8+jl)
        int kp  = (e & 255) * 4;
        int q = row >> 3, jl = row & 7;
        const float* Wq = (q == 0) ? Wf : (q == 1) ? Wi : (q == 2) ? Wo : Wg;
        float4 v = *(const float4*)(Wq + (size_t)(n * 8 + jl) * CDIM + IND + kp);
        float vv[4] = {v.x, v.y, v.z, v.w};
        __half h4[4];
#pragma unroll
        for (int u = 0; u < 4; u++) h4[u] = __float2half(vv[u]);
        u64 hp; __builtin_memcpy(&hp, h4, 8);
        *(u64*)(wsm + (size_t)row * RW_STRIDE + kp) = hp;
    }
    __syncthreads();

    const int lane = tid & 31, wid = tid >> 5;
    const int kg = wid & 1;
    const int wn = (wid >> 1) & 1;
    const int wm = wid >> 2;
    const int arow = ((lane >> 3) & 1) * 8 + (lane & 7);
    const int akof = ((lane >> 4) & 1) * 8;
    const int brow = ((lane >> 4) & 1) * 8 + (lane & 7);
    const int bkof = ((lane >> 3) & 1) * 8;
    const int mrow = lane >> 2;
    const int ncol = (lane & 3) * 2;

    // h-chunk loader geometry: 2 rows per thread (hi only, 16B each)
    int lr[2], lsl[2];
#pragma unroll
    for (int i = 0; i < 2; i++) {
        int e = tid + i * 512;              // 0..1023
        lr[i] = e >> 4; lsl[i] = (e & 15) * 8;
    }

    const int b_act = tid >> 3, jl_act = tid & 7;
    float cst = 0.0f;

    for (int t = 0; t < SEQ; t++) {
        const float* gxb = g_Gx + (((size_t)t * NCTA + n) * 64 + b_act) * 32 + jl_act;
        float gx0 = gxb[0], gx1 = gxb[8], gx2 = gxb[16], gx3 = gxb[24];

        if (t > 0) {
            if (tid == 0) {
                int target = NCTA * t, v;
                do {
                    asm volatile("ld.acquire.gpu.global.s32 %0, [%1];"
                                 : "=r"(v) : "l"(&g_done) : "memory");
                } while (v < target);
            }
            __syncthreads();

            const __half* Ghi = g_Hhi + (size_t)(t - 1) * 65536;

#define RC_ISSUE(buf, ch)                                                        \
    do {                                                                         \
        char* hb = smem + R_HB + (buf) * HBUF_SZ;                                \
        _Pragma("unroll")                                                        \
        for (int i = 0; i < 2; i++) {                                            \
            uint32_t d0 = smem_u32(hb + ((size_t)lr[i] * RH + lsl[i]) * 2);      \
            cpa16(d0, Ghi + (size_t)lr[i] * 1024 + (ch) * 128 + lsl[i]);         \
        }                                                                        \
        CPA_COMMIT();                                                            \
    } while (0)

            float acc0[4] = {0.f, 0.f, 0.f, 0.f};
            float acc1[4] = {0.f, 0.f, 0.f, 0.f};

            RC_ISSUE(0, 0);

#pragma unroll 1
            for (int ch = 0; ch < 8; ch++) {
                CPA_WAIT0();
                __syncthreads();
                if (ch < 7) RC_ISSUE((ch + 1) & 1, ch + 1);

                __half* Hh = (__half*)(smem + R_HB + (ch & 1) * HBUF_SZ);
#pragma unroll
                for (int kk = 0; kk < 4; kk++) {
                    int kid = kg * 4 + kk;
                    uint32_t ah[4], bh[4];
                    ldmx4(ah, smem_u32(Hh + (size_t)(wm * 16 + arow) * RH + kid * 16 + akof));
                    int wk = ch * 128 + kid * 16 + bkof;
                    ldmx4(bh, smem_u32(wsm + (size_t)(wn * 16 + brow) * RW_STRIDE + wk));
                    mma_f16(acc0, ah, bh);
                    mma_f16(acc1, ah, bh + 2);
                }
            }

            // gate pre-activations -> gact[kg][b][c]
            {
                float* ga = gact + kg * 2176;
                int r0 = wm * 16 + mrow;
                int c0 = wn * 16 + ncol;
                *(float2*)(ga + (size_t)r0 * 34 + c0)            = *(float2*)&acc0[0];
                *(float2*)(ga + (size_t)(r0 + 8) * 34 + c0)      = *(float2*)&acc0[2];
                *(float2*)(ga + (size_t)r0 * 34 + c0 + 8)        = *(float2*)&acc1[0];
                *(float2*)(ga + (size_t)(r0 + 8) * 34 + c0 + 8)  = *(float2*)&acc1[2];
            }
            __syncthreads();
        }

        // ---- fused activations + cell update + h write ----
        {
            float fv = gx0, iv = gx1, ov = gx2, gv = gx3;
            if (t > 0) {
                const float* ga0 = gact + (size_t)b_act * 34 + jl_act;
                const float* ga1 = ga0 + 2176;
                fv += ga0[0]  + ga1[0];
                iv += ga0[8]  + ga1[8];
                ov += ga0[16] + ga1[16];
                gv += ga0[24] + ga1[24];
            }
            float f = sigm(fv), ii = sigm(iv), oo = sigm(ov), gt = tanhf(gv);
            cst = f * cst + ii * gt;
            float hv = oo * tanhf(cst);
            __half hh = __float2half(hv);
            size_t idx = ((size_t)t * 64 + b_act) * 1024 + n * 8 + jl_act;
            g_Hhi[idx] = hh;
            g_Hlo[idx] = __float2half(hv - __half2float(hh));
        }

        __syncthreads();
        if (tid == 0)
            asm volatile("red.release.gpu.global.add.s32 [%0], %1;"
                         :: "l"(&g_done), "r"(1) : "memory");
    }
}

// ---------------- launch ----------------
extern "C" void kernel_launch(void* const* d_in, const int* in_sizes, int n_in,
                              void* d_out, int out_size) {
    const float* x  = (const float*)d_in[0];
    const float* Wf = (const float*)d_in[1];
    const float* bf = (const float*)d_in[2];
    const float* Wi = (const float*)d_in[3];
    const float* bi = (const float*)d_in[4];
    const float* Wo = (const float*)d_in[5];
    const float* bo = (const float*)d_in[6];
    const float* Wg = (const float*)d_in[7];
    const float* bg = (const float*)d_in[8];
    const float* Wy = (const float*)d_in[9];
    const float* by = (const float*)d_in[10];
    float* out = (float*)d_out;

    cudaFuncSetAttribute(k_recur, cudaFuncAttributeMaxDynamicSharedMemorySize, SMEM_R);
    cudaFuncSetAttribute(k_tgemm, cudaFuncAttributeMaxDynamicSharedMemorySize, TG_SMEM);

    k_init<<<1, 32>>>();

    // converts for the bulk GEMMs
    k_cvt_split<<<4096, 256>>>((const float4*)x, (long)SEQ * BATCH * IND / 4);
    k_cvt_wall<<<4096, 128>>>(Wf, bf, Wi, bi, Wo, bo, Wg, bg);
    k_cvt_one<<<512, 256>>>((const float4*)Wy, (long)OUTD * HID / 4);

    // pregemm: Gx = X @ W_all^T + b_all -> permuted [t][n][b][c]
    k_tgemm<<<dim3(32, 256), 256, TG_SMEM>>>(nullptr, nullptr, IND, 1);

    // recurrence (tensor-core, persistent, single-pass fp16)
    k_recur<<<NCTA, 512, SMEM_R>>>(Wf, Wi, Wo, Wg);

    // out = H @ Wy^T + by  (A = g_Hhi/g_Hlo written by k_recur)
    k_tgemm<<<dim3(4, 256), 256, TG_SMEM>>>(by, out, HID, 0);
}

// round 17
// speedup vs baseline: 1.5142x; 1.0754x over previous
#include <cuda_runtime.h>
#include <cuda_fp16.h>
#include <math.h>
#include <stdint.h>

// Problem dims (fixed)
#define SEQ   512
#define BATCH 64
#define IND   512
#define HID   1024
#define OUTD  512
#define CDIM  1536

#define NCTA  128          // recurrence CTAs: CTA n owns cols c=q*8+jl, j=n*8+jl

typedef unsigned long long u64;

// ---- k_recur smem layout (bytes) ----
#define RW_STRIDE 1032     // W smem row stride (fp16 elems)
#define RHE       264      // h smem row stride (fp16 elems) for 256-k chunks
#define R_W   0                       // 32 x 1032 x 2B = 66048
#define R_HB  66048                   // 3 bufs x 64x264x2B = 3x33792
#define HBUF_SZ 33792
#define R_GACT 167424                 // float[2][64*34] = 17408
#define SMEM_R 184832

// ---- k_tgemm smem (3-stage cp.async pipeline, 3 tiles/stage) ----
#define TS 40
#define TG_TILE_B (128 * TS * 2)      // 10240 B per tile
#define TG_STAGE_B (3 * TG_TILE_B)    // 30720 B per stage (A_hi, A_lo, B)
#define TG_SMEM (3 * TG_STAGE_B)      // 92160 B

// ---------------- scratch ----------------
__device__ float g_Gx  [(size_t)SEQ * NCTA * BATCH * 32];   // [t][n][b][c], c=q*8+jl
__device__ int   g_done;
__device__ __half g_Xhi [(size_t)SEQ * BATCH * IND];
__device__ __half g_Xlo [(size_t)SEQ * BATCH * IND];
__device__ __half g_WAh [(size_t)4096 * 512];               // W_all input part, single fp16
__device__ __half g_Hhi [(size_t)SEQ * BATCH * HID];        // h for step t at rows t*64+b
__device__ __half g_Hlo [(size_t)SEQ * BATCH * HID];        // residual (out-GEMM only)
__device__ __half g_Wyh [(size_t)OUTD * HID];               // Wy single fp16
__device__ float g_ball[4096];

static __device__ __forceinline__ float sigm(float x) { return 1.0f / (1.0f + __expf(-x)); }

// ---------------- mma.sync / cp.async helpers ----------------
static __device__ __forceinline__ uint32_t smem_u32(const void* p) {
    uint32_t a;
    asm("{ .reg .u64 t; cvta.to.shared.u64 t, %1; cvt.u32.u64 %0, t; }" : "=r"(a) : "l"(p));
    return a;
}
static __device__ __forceinline__ void ldmx4(uint32_t* r, uint32_t addr) {
    asm volatile("ldmatrix.sync.aligned.m8n8.x4.shared.b16 {%0,%1,%2,%3}, [%4];"
                 : "=r"(r[0]), "=r"(r[1]), "=r"(r[2]), "=r"(r[3]) : "r"(addr));
}
static __device__ __forceinline__ void mma_f16(float* c, const uint32_t* a, const uint32_t* b) {
    asm volatile(
        "mma.sync.aligned.m16n8k16.row.col.f32.f16.f16.f32 "
        "{%0,%1,%2,%3}, {%4,%5,%6,%7}, {%8,%9}, {%0,%1,%2,%3};"
        : "+f"(c[0]), "+f"(c[1]), "+f"(c[2]), "+f"(c[3])
        : "r"(a[0]), "r"(a[1]), "r"(a[2]), "r"(a[3]), "r"(b[0]), "r"(b[1]));
}
static __device__ __forceinline__ void cpa16(uint32_t dst, const void* src) {
    asm volatile("cp.async.cg.shared.global [%0], [%1], 16;" :: "r"(dst), "l"(src));
}
#define CPA_COMMIT() asm volatile("cp.async.commit_group;" ::: "memory")
#define CPA_WAIT0()  asm volatile("cp.async.wait_group 0;" ::: "memory")
#define CPA_WAIT1()  asm volatile("cp.async.wait_group 1;" ::: "memory")

__global__ void k_init() { if (threadIdx.x == 0) g_done = 0; }

// =====================================================================
// converters
// =====================================================================
// X: fp32 -> (fp16 hi, fp16 lo)
__global__ void k_cvt_split(const float4* __restrict__ src, long n4)
{
    u64* hi = (u64*)g_Xhi; u64* lo = (u64*)g_Xlo;
    long i = (long)blockIdx.x * blockDim.x + threadIdx.x;
    long stride = (long)gridDim.x * blockDim.x;
    for (; i < n4; i += stride) {
        float4 v = src[i];
        float vv[4] = {v.x, v.y, v.z, v.w};
        __half h[4], l[4];
#pragma unroll
        for (int j = 0; j < 4; j++) {
            h[j] = __float2half(vv[j]);
            l[j] = __float2half(vv[j] - __half2float(h[j]));
        }
        u64 hp, lp;
        __builtin_memcpy(&hp, h, 8); __builtin_memcpy(&lp, l, 8);
        hi[i] = hp; lo[i] = lp;
    }
}

// Wy: fp32 -> single fp16
__global__ void k_cvt_one(const float4* __restrict__ src, long n4)
{
    u64* dst = (u64*)g_Wyh;
    long i = (long)blockIdx.x * blockDim.x + threadIdx.x;
    long stride = (long)gridDim.x * blockDim.x;
    for (; i < n4; i += stride) {
        float4 v = src[i];
        float vv[4] = {v.x, v.y, v.z, v.w};
        __half h[4];
#pragma unroll
        for (int j = 0; j < 4; j++) h[j] = __float2half(vv[j]);
        u64 hp; __builtin_memcpy(&hp, h, 8);
        dst[i] = hp;
    }
}

// gather W_all input part (cols 0..511, single fp16) + bias
__global__ void k_cvt_wall(
    const float* __restrict__ Wf, const float* __restrict__ bf,
    const float* __restrict__ Wi, const float* __restrict__ bi,
    const float* __restrict__ Wo, const float* __restrict__ bo,
    const float* __restrict__ Wg, const float* __restrict__ bg)
{
    int n = blockIdx.x;                 // 0..4095
    int q = n >> 10, j = n & 1023;
    const float* Wq = (q == 0) ? Wf : (q == 1) ? Wi : (q == 2) ? Wo : Wg;
    const float* bq = (q == 0) ? bf : (q == 1) ? bi : (q == 2) ? bo : bg;
    int k = threadIdx.x * 4;
    float4 v = *(const float4*)(Wq + (size_t)j * CDIM + k);
    float vv[4] = {v.x, v.y, v.z, v.w};
    __half h[4];
#pragma unroll
    for (int t = 0; t < 4; t++) h[t] = __float2half(vv[t]);
    u64 hp; __builtin_memcpy(&hp, h, 8);
    *(u64*)(g_WAh + (size_t)n * 512 + k) = hp;
    if (threadIdx.x == 0) g_ball[n] = bq[j];
}

// =====================================================================
// k_tgemm: C = (Ahi+Alo) @ B^T + bias, fp16 2-pass mma.sync,
// 3-stage cp.async pipeline. CTA tile 128x128, 8 warps (4m x 2n).
// mode 1: A=X, B=WAh -> g_Gx permuted;  mode 0: A=H, B=Wyh -> outp rows
// =====================================================================
__global__ __launch_bounds__(256) void k_tgemm(
    const float* __restrict__ bias_ext, float* __restrict__ outp, int K, int mode)
{
    extern __shared__ char tgs[];

    const int tid  = threadIdx.x;
    const int lane = tid & 31, w = tid >> 5;
    const int wm = w & 3, wn = w >> 2;
    const int m0 = blockIdx.y * 128, n0 = blockIdx.x * 128;

    const __half* bases[3];
    const float* bias;
    if (mode == 1) {
        bases[0] = g_Xhi + (size_t)m0 * K;  bases[1] = g_Xlo + (size_t)m0 * K;
        bases[2] = g_WAh + (size_t)n0 * K;
        bias = g_ball;
    } else {
        bases[0] = g_Hhi + (size_t)m0 * K;  bases[1] = g_Hlo + (size_t)m0 * K;
        bases[2] = g_Wyh + (size_t)n0 * K;
        bias = bias_ext;
    }

    float acc[2][8][4];
#pragma unroll
    for (int mt = 0; mt < 2; mt++)
#pragma unroll
        for (int nt = 0; nt < 8; nt++)
#pragma unroll
            for (int f = 0; f < 4; f++) acc[mt][nt][f] = 0.0f;

    const int arow = ((lane >> 3) & 1) * 8 + (lane & 7);
    const int akof = ((lane >> 4) & 1) * 8;
    const int brow = ((lane >> 4) & 1) * 8 + (lane & 7);
    const int bkof = ((lane >> 3) & 1) * 8;

    // loader: 6 cp.async(16B) per thread per chunk (3 tiles x 128 r x 4 slots)
    int ld_tile[6], ld_r[6], ld_slot[6];
#pragma unroll
    for (int i = 0; i < 6; i++) {
        int e = tid + i * 256;
        ld_tile[i] = e >> 9; ld_r[i] = (e >> 2) & 127; ld_slot[i] = e & 3;
    }

    const int chunks = K >> 5;

#define TG_ISSUE(stage, ch)                                                     \
    do {                                                                        \
        char* sb = tgs + (stage) * TG_STAGE_B;                                  \
        _Pragma("unroll")                                                       \
        for (int i = 0; i < 6; i++) {                                           \
            uint32_t dst = smem_u32(sb + ld_tile[i] * TG_TILE_B                 \
                                    + (ld_r[i] * TS + ld_slot[i] * 8) * 2);     \
            cpa16(dst, bases[ld_tile[i]] + (size_t)ld_r[i] * K                  \
                       + (ch) * 32 + ld_slot[i] * 8);                           \
        }                                                                       \
        CPA_COMMIT();                                                           \
    } while (0)

    TG_ISSUE(0, 0);
    if (chunks > 1) TG_ISSUE(1, 1); else CPA_COMMIT();

    for (int ch = 0; ch < chunks; ch++) {
        if (ch + 1 < chunks) CPA_WAIT1(); else CPA_WAIT0();
        __syncthreads();
        if (ch + 2 < chunks) TG_ISSUE((ch + 2) % 3, ch + 2);

        char* sb = tgs + (ch % 3) * TG_STAGE_B;
        __half* smA[2] = { (__half*)(sb), (__half*)(sb + TG_TILE_B) };
        __half* smB   = (__half*)(sb + 2 * TG_TILE_B);

#pragma unroll
        for (int kstep = 0; kstep < 2; kstep++) {
            uint32_t afr[2][2][4];   // [mt][hi/lo][4]
#pragma unroll
            for (int mt = 0; mt < 2; mt++)
#pragma unroll
                for (int s = 0; s < 2; s++)
                    ldmx4(afr[mt][s], smem_u32(
                        smA[s] + (wm * 32 + mt * 16 + arow) * TS + akof + kstep * 16));
            uint32_t bfr[8][2];      // [nt][2]
#pragma unroll
            for (int ntp = 0; ntp < 4; ntp++) {
                uint32_t r4[4];
                ldmx4(r4, smem_u32(
                    smB + (wn * 64 + ntp * 16 + brow) * TS + bkof + kstep * 16));
                bfr[ntp * 2][0]     = r4[0];
                bfr[ntp * 2][1]     = r4[1];
                bfr[ntp * 2 + 1][0] = r4[2];
                bfr[ntp * 2 + 1][1] = r4[3];
            }
#pragma unroll
            for (int mt = 0; mt < 2; mt++)
#pragma unroll
                for (int nt = 0; nt < 8; nt++) {
                    mma_f16(acc[mt][nt], afr[mt][0], bfr[nt]);  // hi pass
                    mma_f16(acc[mt][nt], afr[mt][1], bfr[nt]);  // lo pass
                }
        }
        __syncthreads();
    }

    const int mrow = lane >> 2;
    const int ncol = (lane & 3) * 2;
#pragma unroll
    for (int mt = 0; mt < 2; mt++) {
#pragma unroll
        for (int nt = 0; nt < 8; nt++) {
            int nloc = wn * 64 + nt * 8 + ncol;
            int nglb = n0 + nloc;
            float2 bv = {bias[nglb], bias[nglb + 1]};
#pragma unroll
            for (int half = 0; half < 2; half++) {
                int gm = m0 + wm * 32 + mt * 16 + mrow + half * 8;
                float2 v;
                v.x = acc[mt][nt][half * 2 + 0] + bv.x;
                v.y = acc[mt][nt][half * 2 + 1] + bv.y;
                if (mode == 0) {
                    *(float2*)(outp + (size_t)gm * OUTD + nglb) = v;
                } else {
                    int q  = n0 >> 10;
                    int jj = (n0 & 1023) + nloc;
                    int ntidx = jj >> 3, jl = jj & 7;
                    int tt = gm >> 6, b = gm & 63;
                    *(float2*)(g_Gx + (((size_t)tt * NCTA + ntidx) * 64 + b) * 32
                               + q * 8 + jl) = v;
                }
            }
        }
    }
}

// =====================================================================
// k_recur: PERSISTENT recurrence, fp16 single-pass mma.sync.
// 128 CTAs x 512 thr (16 warps: 4m x 2n x 2kg). 4 h-chunks of 256k,
// 3 smem buffers, 2 cp.async transfers in flight. W fp16 resident in
// smem; c in regs; one acquire/release global sync per step.
// =====================================================================
__global__ __launch_bounds__(512, 1) void k_recur(
    const float* __restrict__ Wf, const float* __restrict__ Wi,
    const float* __restrict__ Wo, const float* __restrict__ Wg)
{
    extern __shared__ char smem[];
    __half* wsm  = (__half*)(smem + R_W);      // [32 c][1024 k] stride 1032
    float*  gact = (float*)(smem + R_GACT);    // [2 kg][64 b][34]

    const int tid = threadIdx.x;
    const int n   = blockIdx.x;

    // ---- one-time: convert W slice to single fp16 in smem ----
#pragma unroll 4
    for (int i = 0; i < 16; i++) {
        int e = tid + i * 512;              // 0..8191, float4 each
        int row = e >> 8;                   // 0..31  (c = q*8+jl)
        int kp  = (e & 255) * 4;
        int q = row >> 3, jl = row & 7;
        const float* Wq = (q == 0) ? Wf : (q == 1) ? Wi : (q == 2) ? Wo : Wg;
        float4 v = *(const float4*)(Wq + (size_t)(n * 8 + jl) * CDIM + IND + kp);
        float vv[4] = {v.x, v.y, v.z, v.w};
        __half h4[4];
#pragma unroll
        for (int u = 0; u < 4; u++) h4[u] = __float2half(vv[u]);
        u64 hp; __builtin_memcpy(&hp, h4, 8);
        *(u64*)(wsm + (size_t)row * RW_STRIDE + kp) = hp;
    }
    __syncthreads();

    const int lane = tid & 31, wid = tid >> 5;
    const int kg = wid & 1;
    const int wn = (wid >> 1) & 1;
    const int wm = wid >> 2;
    const int arow = ((lane >> 3) & 1) * 8 + (lane & 7);
    const int akof = ((lane >> 4) & 1) * 8;
    const int brow = ((lane >> 4) & 1) * 8 + (lane & 7);
    const int bkof = ((lane >> 3) & 1) * 8;
    const int mrow = lane >> 2;
    const int ncol = (lane & 3) * 2;

    // h-chunk loader geometry: 4 x 16B per thread per 256-k chunk
    // chunk = 64 rows x 256 fp16 = 2048 slots of 16B
    int lr[4], lsl[4];
#pragma unroll
    for (int i = 0; i < 4; i++) {
        int e = tid + i * 512;              // 0..2047
        lr[i] = e >> 5; lsl[i] = (e & 31) * 8;
    }

    const int b_act = tid >> 3, jl_act = tid & 7;
    float cst = 0.0f;

    for (int t = 0; t < SEQ; t++) {
        const float* gxb = g_Gx + (((size_t)t * NCTA + n) * 64 + b_act) * 32 + jl_act;
        float gx0 = gxb[0], gx1 = gxb[8], gx2 = gxb[16], gx3 = gxb[24];

        if (t > 0) {
            if (tid == 0) {
                int target = NCTA * t, v;
                do {
                    asm volatile("ld.acquire.gpu.global.s32 %0, [%1];"
                                 : "=r"(v) : "l"(&g_done) : "memory");
                } while (v < target);
            }
            __syncthreads();

            const __half* Ghi = g_Hhi + (size_t)(t - 1) * 65536;

#define RC_ISSUE(buf, ch)                                                        \
    do {                                                                         \
        char* hb = smem + R_HB + (buf) * HBUF_SZ;                                \
        _Pragma("unroll")                                                        \
        for (int i = 0; i < 4; i++) {                                            \
            uint32_t d0 = smem_u32(hb + ((size_t)lr[i] * RHE + lsl[i]) * 2);     \
            cpa16(d0, Ghi + (size_t)lr[i] * 1024 + (ch) * 256 + lsl[i]);         \
        }                                                                        \
        CPA_COMMIT();                                                            \
    } while (0)

            float acc0[4] = {0.f, 0.f, 0.f, 0.f};
            float acc1[4] = {0.f, 0.f, 0.f, 0.f};

            RC_ISSUE(0, 0);
            RC_ISSUE(1, 1);

#pragma unroll 1
            for (int ch = 0; ch < 4; ch++) {
                if (ch + 1 < 4) CPA_WAIT1(); else CPA_WAIT0();
                __syncthreads();
                if (ch + 2 < 4) RC_ISSUE((ch + 2) % 3, ch + 2);

                __half* Hh = (__half*)(smem + R_HB + (ch % 3) * HBUF_SZ);
#pragma unroll
                for (int kk = 0; kk < 8; kk++) {
                    int kid = kg * 8 + kk;    // kstep within the 256-k chunk
                    uint32_t ah[4], bh[4];
                    ldmx4(ah, smem_u32(Hh + (size_t)(wm * 16 + arow) * RHE + kid * 16 + akof));
                    int wk = ch * 256 + kid * 16 + bkof;
                    ldmx4(bh, smem_u32(wsm + (size_t)(wn * 16 + brow) * RW_STRIDE + wk));
                    mma_f16(acc0, ah, bh);
                    mma_f16(acc1, ah, bh + 2);
                }
            }

            // gate pre-activations -> gact[kg][b][c]
            {
                float* ga = gact + kg * 2176;
                int r0 = wm * 16 + mrow;
                int c0 = wn * 16 + ncol;
                *(float2*)(ga + (size_t)r0 * 34 + c0)            = *(float2*)&acc0[0];
                *(float2*)(ga + (size_t)(r0 + 8) * 34 + c0)      = *(float2*)&acc0[2];
                *(float2*)(ga + (size_t)r0 * 34 + c0 + 8)        = *(float2*)&acc1[0];
                *(float2*)(ga + (size_t)(r0 + 8) * 34 + c0 + 8)  = *(float2*)&acc1[2];
            }
            __syncthreads();
        }

        // ---- fused activations + cell update + h write ----
        {
            float fv = gx0, iv = gx1, ov = gx2, gv = gx3;
            if (t > 0) {
                const float* ga0 = gact + (size_t)b_act * 34 + jl_act;
                const float* ga1 = ga0 + 2176;
                fv += ga0[0]  + ga1[0];
                iv += ga0[8]  + ga1[8];
                ov += ga0[16] + ga1[16];
                gv += ga0[24] + ga1[24];
            }
            float f = sigm(fv), ii = sigm(iv), oo = sigm(ov), gt = tanhf(gv);
            cst = f * cst + ii * gt;
            float hv = oo * tanhf(cst);
            __half hh = __float2half(hv);
            size_t idx = ((size_t)t * 64 + b_act) * 1024 + n * 8 + jl_act;
            g_Hhi[idx] = hh;
            g_Hlo[idx] = __float2half(hv - __half2float(hh));
        }

        __syncthreads();
        if (tid == 0)
            asm volatile("red.release.gpu.global.add.s32 [%0], %1;"
                         :: "l"(&g_done), "r"(1) : "memory");
    }
}

// ---------------- launch ----------------
extern "C" void kernel_launch(void* const* d_in, const int* in_sizes, int n_in,
                              void* d_out, int out_size) {
    const float* x  = (const float*)d_in[0];
    const float* Wf = (const float*)d_in[1];
    const float* bf = (const float*)d_in[2];
    const float* Wi = (const float*)d_in[3];
    const float* bi = (const float*)d_in[4];
    const float* Wo = (const float*)d_in[5];
    const float* bo = (const float*)d_in[6];
    const float* Wg = (const float*)d_in[7];
    const float* bg = (const float*)d_in[8];
    const float* Wy = (const float*)d_in[9];
    const float* by = (const float*)d_in[10];
    float* out = (float*)d_out;

    cudaFuncSetAttribute(k_recur, cudaFuncAttributeMaxDynamicSharedMemorySize, SMEM_R);
    cudaFuncSetAttribute(k_tgemm, cudaFuncAttributeMaxDynamicSharedMemorySize, TG_SMEM);

    k_init<<<1, 32>>>();

    // converts for the bulk GEMMs
    k_cvt_split<<<4096, 256>>>((const float4*)x, (long)SEQ * BATCH * IND / 4);
    k_cvt_wall<<<4096, 128>>>(Wf, bf, Wi, bi, Wo, bo, Wg, bg);
    k_cvt_one<<<512, 256>>>((const float4*)Wy, (long)OUTD * HID / 4);

    // pregemm: Gx = X @ W_all^T + b_all -> permuted [t][n][b][c]
    k_tgemm<<<dim3(32, 256), 256, TG_SMEM>>>(nullptr, nullptr, IND, 1);

    // recurrence (tensor-core, persistent, single-pass fp16)
    k_recur<<<NCTA, 512, SMEM_R>>>(Wf, Wi, Wo, Wg);

    // out = H @ Wy^T + by  (A = g_Hhi/g_Hlo written by k_recur)
    k_tgemm<<<dim3(4, 256), 256, TG_SMEM>>>(by, out, HID, 0);
}